// round 3
// baseline (speedup 1.0000x reference)
#include <cuda_runtime.h>

#define BATCH 64
#define NOBJ  64
#define HID   256
#define KT    32
#define OUTC  28

// Scratch (device globals; no allocation allowed)
__device__ float g_U[BATCH * NOBJ * HID];     // 4 MB: xf @ g1_w[0:26]
__device__ float g_V[BATCH * NOBJ * HID];     // 4 MB: xjq @ g1_w[26:180] + g1_b
__device__ float g_PART[BATCH * NOBJ * HID];  // 4 MB: per-(b,a1) partial pair sums

// ---------------------------------------------------------------------------
// Packed f32x2 helpers (sm_100+ PTX): 2 MACs per issued instruction.
// ---------------------------------------------------------------------------
__device__ __forceinline__ unsigned long long ffma2(unsigned long long a,
                                                    unsigned long long b,
                                                    unsigned long long c) {
    unsigned long long d;
    asm("fma.rn.f32x2 %0, %1, %2, %3;" : "=l"(d) : "l"(a), "l"(b), "l"(c));
    return d;
}
__device__ __forceinline__ unsigned long long pack2(float x) {
    unsigned long long r;
    asm("mov.b64 %0, {%1, %1};" : "=l"(r) : "f"(x));
    return r;
}
__device__ __forceinline__ void unpack2(unsigned long long v, float& lo, float& hi) {
    asm("mov.b64 {%0, %1}, %2;" : "=f"(lo), "=f"(hi) : "l"(v));
}

// ---------------------------------------------------------------------------
// Kernel 1: build U[b, j, :] and V[b, i, :] (first g layer split by linearity)
// grid = (NOBJ, BATCH), block = 256 (one thread per output channel)
// ---------------------------------------------------------------------------
__global__ void prep_kernel(const float* __restrict__ x,
                            const float* __restrict__ qst,
                            const float* __restrict__ g1_w,
                            const float* __restrict__ g1_b) {
    __shared__ float sxf[26];
    __shared__ float sq[128];
    const int b = blockIdx.y;
    const int row = blockIdx.x;  // spatial object index j = 0..63
    const int t = threadIdx.x;

    if (t < 24) sxf[t] = x[(b * 24 + t) * 64 + row];
    if (t == 24) sxf[24] = ((float)row * 0.125f - 4.0f) * 0.25f;        // cx = (j/8.0 - 4)/4
    if (t == 25) sxf[25] = ((float)(row & 7) - 4.0f) * 0.25f;           // cy = (j%8 - 4)/4
    if (t >= 128) sq[t - 128] = qst[b * 128 + (t - 128)];
    __syncthreads();

    float u = 0.0f;
    float v = g1_b[t];
#pragma unroll
    for (int p = 0; p < 26; p++) {
        u += sxf[p] * g1_w[p * HID + t];
        v += sxf[p] * g1_w[(26 + p) * HID + t];
    }
#pragma unroll 8
    for (int q = 0; q < 128; q++) v += sq[q] * g1_w[(52 + q) * HID + t];

    g_U[(b * NOBJ + row) * HID + t] = u;
    g_V[(b * NOBJ + row) * HID + t] = v;
}

// ---------------------------------------------------------------------------
// Kernel 2: fused pair MLP.  One block per (a1, b).
//   h1[j, :] = relu(U[b,j,:] + V[b,a1,:])                (64 x 256 in smem)
//   h2 = relu(h1 @ W2 + b2); h3 = relu(h2 @ W3 + b3); h4 = relu(h3 @ W4 + b4)
//   PART[b,a1,:] = sum_j h4[j,:]
// Thread map: warp w -> rows [8w, 8w+8); lane l -> column-pairs {l+32*jj}
// (cols 2cp, 2cp+1) so weight loads are conflict-free LDS.64 and A loads are
// warp-uniform broadcasts. Accumulators are f32x2.
// ---------------------------------------------------------------------------
__global__ void __launch_bounds__(256, 1)
pair_kernel(const float* __restrict__ w2, const float* __restrict__ b2,
            const float* __restrict__ w3, const float* __restrict__ b3,
            const float* __restrict__ w4, const float* __restrict__ b4) {
    extern __shared__ float smem[];
    float* bufA = smem;                      // 64*256
    float* bufB = smem + NOBJ * HID;         // 64*256
    float* wt   = smem + 2 * NOBJ * HID;     // KT*256 weight tile
    float* vrow = wt + KT * HID;             // 256

    const int a1 = blockIdx.x;
    const int b  = blockIdx.y;
    const int t  = threadIdx.x;
    const int wi = t >> 5;       // warp id -> row group
    const int l  = t & 31;       // lane -> column pairs
    const int r0 = wi * 8;

    vrow[t] = g_V[(b * NOBJ + a1) * HID + t];
    __syncthreads();

    const float* Ub = g_U + (size_t)b * NOBJ * HID;
    for (int idx = t; idx < NOBJ * HID; idx += 256) {
        float hv = Ub[idx] + vrow[idx & (HID - 1)];
        bufA[idx] = hv > 0.0f ? hv : 0.0f;
    }
    __syncthreads();

    const float* Ws[3] = {w2, w3, w4};
    const float* Bs[3] = {b2, b3, b4};
    float* bin = bufA;
    float* bout = bufB;

    for (int layer = 0; layer < 3; layer++) {
        const float* W = Ws[layer];

        unsigned long long acc[8][4];
#pragma unroll
        for (int i = 0; i < 8; i++)
#pragma unroll
            for (int jj = 0; jj < 4; jj++) acc[i][jj] = 0ull;  // (0.f, 0.f)

        for (int kb = 0; kb < HID / KT; kb++) {
            // stage KT x 256 weight tile into smem (float4 vectorized)
            const float4* src = (const float4*)(W + kb * KT * HID);
            float4* dst = (float4*)wt;
            for (int i = t; i < KT * HID / 4; i += 256) dst[i] = src[i];
            __syncthreads();

            const float* arow = bin + kb * KT;
#pragma unroll 4
            for (int k = 0; k < KT; k++) {
                unsigned long long a2[8];
#pragma unroll
                for (int i = 0; i < 8; i++)
                    a2[i] = pack2(arow[(r0 + i) * HID + k]);  // warp-uniform broadcast
#pragma unroll
                for (int jj = 0; jj < 4; jj++) {
                    unsigned long long wv =
                        *(const unsigned long long*)(wt + k * HID + 2 * (l + 32 * jj));
#pragma unroll
                    for (int i = 0; i < 8; i++) acc[i][jj] = ffma2(a2[i], wv, acc[i][jj]);
                }
            }
            __syncthreads();
        }

        // epilogue: bias + relu -> bout
        const float* bias = Bs[layer];
#pragma unroll
        for (int jj = 0; jj < 4; jj++) {
            const int c = 2 * (l + 32 * jj);
            const float2 bb = *(const float2*)(bias + c);
#pragma unroll
            for (int i = 0; i < 8; i++) {
                float lo, hi;
                unpack2(acc[i][jj], lo, hi);
                lo += bb.x;
                hi += bb.y;
                float2 o;
                o.x = lo > 0.0f ? lo : 0.0f;
                o.y = hi > 0.0f ? hi : 0.0f;
                *(float2*)(bout + (r0 + i) * HID + c) = o;
            }
        }
        __syncthreads();
        float* tmp = bin; bin = bout; bout = tmp;
    }

    // bin holds h4 (64 x 256): column sums (bank-conflict-free: bank = t%32)
    float s = 0.0f;
#pragma unroll 8
    for (int row = 0; row < NOBJ; row++) s += bin[row * HID + t];
    g_PART[((size_t)b * NOBJ + a1) * HID + t] = s;
}

// ---------------------------------------------------------------------------
// Kernel 3: reduce partials -> xg, f MLP, log_softmax. One block per batch.
// ---------------------------------------------------------------------------
__global__ void final_kernel(const float* __restrict__ f1_w, const float* __restrict__ f1_b,
                             const float* __restrict__ f2_w, const float* __restrict__ f2_b,
                             const float* __restrict__ f3_w, const float* __restrict__ f3_b,
                             float* __restrict__ out) {
    __shared__ float sa[HID];
    __shared__ float sb[HID];
    __shared__ float sl[OUTC];
    __shared__ float lse;
    const int b = blockIdx.x;
    const int t = threadIdx.x;

    // xg[b, t] = sum over a1 of PART[b, a1, t]
    float s = 0.0f;
    const float* P = g_PART + (size_t)b * NOBJ * HID;
#pragma unroll 8
    for (int a1 = 0; a1 < NOBJ; a1++) s += P[a1 * HID + t];
    sa[t] = s;
    __syncthreads();

    // f1
    float acc = f1_b[t];
#pragma unroll 8
    for (int c = 0; c < HID; c++) acc += sa[c] * f1_w[c * HID + t];
    sb[t] = acc > 0.0f ? acc : 0.0f;
    __syncthreads();

    // f2
    acc = f2_b[t];
#pragma unroll 8
    for (int c = 0; c < HID; c++) acc += sb[c] * f2_w[c * HID + t];
    float y2 = acc > 0.0f ? acc : 0.0f;
    __syncthreads();
    sa[t] = y2;
    __syncthreads();

    // f3 logits
    if (t < OUTC) {
        acc = f3_b[t];
#pragma unroll 8
        for (int c = 0; c < HID; c++) acc += sa[c] * f3_w[c * OUTC + t];
        sl[t] = acc;
    }
    __syncthreads();

    if (t == 0) {
        float m = sl[0];
        for (int i = 1; i < OUTC; i++) m = fmaxf(m, sl[i]);
        float se = 0.0f;
        for (int i = 0; i < OUTC; i++) se += expf(sl[i] - m);
        lse = m + logf(se);
    }
    __syncthreads();
    if (t < OUTC) out[b * OUTC + t] = sl[t] - lse;
}

// ---------------------------------------------------------------------------
extern "C" void kernel_launch(void* const* d_in, const int* in_sizes, int n_in,
                              void* d_out, int out_size) {
    const float* x    = (const float*)d_in[0];
    const float* qst  = (const float*)d_in[1];
    const float* g1_w = (const float*)d_in[2];
    const float* g1_b = (const float*)d_in[3];
    const float* g2_w = (const float*)d_in[4];
    const float* g2_b = (const float*)d_in[5];
    const float* g3_w = (const float*)d_in[6];
    const float* g3_b = (const float*)d_in[7];
    const float* g4_w = (const float*)d_in[8];
    const float* g4_b = (const float*)d_in[9];
    const float* f1_w = (const float*)d_in[10];
    const float* f1_b = (const float*)d_in[11];
    const float* f2_w = (const float*)d_in[12];
    const float* f2_b = (const float*)d_in[13];
    const float* f3_w = (const float*)d_in[14];
    const float* f3_b = (const float*)d_in[15];
    float* out = (float*)d_out;

    const int smem_bytes = (2 * NOBJ * HID + KT * HID + HID) * (int)sizeof(float);
    cudaFuncSetAttribute(pair_kernel, cudaFuncAttributeMaxDynamicSharedMemorySize,
                         smem_bytes);

    prep_kernel<<<dim3(NOBJ, BATCH), 256>>>(x, qst, g1_w, g1_b);
    pair_kernel<<<dim3(NOBJ, BATCH), 256, smem_bytes>>>(g2_w, g2_b, g3_w, g3_b,
                                                        g4_w, g4_b);
    final_kernel<<<BATCH, 256>>>(f1_w, f1_b, f2_w, f2_b, f3_w, f3_b, out);
}

// round 4
// speedup vs baseline: 1.0001x; 1.0001x over previous
#include <cuda_runtime.h>

#define BATCH 64
#define NOBJ  64
#define HID   256
#define KT    32
#define OUTC  28

// Scratch (device globals; no allocation allowed)
__device__ float g_U[BATCH * NOBJ * HID];     // 4 MB: xf @ g1_w[0:26]
__device__ float g_V[BATCH * NOBJ * HID];     // 4 MB: xjq @ g1_w[26:180] + g1_b
__device__ float g_PART[BATCH * NOBJ * HID];  // 4 MB: per-(b,a1) partial pair sums

// ---------------------------------------------------------------------------
// Packed f32x2 helpers (sm_100+ PTX): 2 MACs per issued instruction.
// ---------------------------------------------------------------------------
__device__ __forceinline__ unsigned long long ffma2(unsigned long long a,
                                                    unsigned long long b,
                                                    unsigned long long c) {
    unsigned long long d;
    asm("fma.rn.f32x2 %0, %1, %2, %3;" : "=l"(d) : "l"(a), "l"(b), "l"(c));
    return d;
}
__device__ __forceinline__ unsigned long long pack2(float x) {
    unsigned long long r;
    asm("mov.b64 %0, {%1, %1};" : "=l"(r) : "f"(x));
    return r;
}
__device__ __forceinline__ void unpack2(unsigned long long v, float& lo, float& hi) {
    asm("mov.b64 {%0, %1}, %2;" : "=f"(lo), "=f"(hi) : "l"(v));
}

// ---------------------------------------------------------------------------
// Kernel 1: build U[b, j, :] and V[b, i, :] (first g layer split by linearity)
// grid = (NOBJ, BATCH), block = 256 (one thread per output channel)
// ---------------------------------------------------------------------------
__global__ void prep_kernel(const float* __restrict__ x,
                            const float* __restrict__ qst,
                            const float* __restrict__ g1_w,
                            const float* __restrict__ g1_b) {
    __shared__ float sxf[26];
    __shared__ float sq[128];
    const int b = blockIdx.y;
    const int row = blockIdx.x;  // spatial object index j = 0..63
    const int t = threadIdx.x;

    if (t < 24) sxf[t] = x[(b * 24 + t) * 64 + row];
    if (t == 24) sxf[24] = ((float)row * 0.125f - 4.0f) * 0.25f;        // cx = (j/8.0 - 4)/4
    if (t == 25) sxf[25] = ((float)(row & 7) - 4.0f) * 0.25f;           // cy = (j%8 - 4)/4
    if (t >= 128) sq[t - 128] = qst[b * 128 + (t - 128)];
    __syncthreads();

    float u = 0.0f;
    float v = g1_b[t];
#pragma unroll
    for (int p = 0; p < 26; p++) {
        u += sxf[p] * g1_w[p * HID + t];
        v += sxf[p] * g1_w[(26 + p) * HID + t];
    }
#pragma unroll 8
    for (int q = 0; q < 128; q++) v += sq[q] * g1_w[(52 + q) * HID + t];

    g_U[(b * NOBJ + row) * HID + t] = u;
    g_V[(b * NOBJ + row) * HID + t] = v;
}

// ---------------------------------------------------------------------------
// Kernel 2: fused pair MLP.  One block per (a1, b).
//   h1[j, :] = relu(U[b,j,:] + V[b,a1,:])                (64 x 256 in smem)
//   h2 = relu(h1 @ W2 + b2); h3 = relu(h2 @ W3 + b3); h4 = relu(h3 @ W4 + b4)
//   PART[b,a1,:] = sum_j h4[j,:]
// Thread map: warp w -> rows [8w, 8w+8); lane l -> column-pairs {l+32*jj}
// (cols 2cp, 2cp+1) so weight loads are conflict-free LDS.64 and A loads are
// warp-uniform broadcasts. Accumulators are f32x2.
// ---------------------------------------------------------------------------
__global__ void __launch_bounds__(256, 1)
pair_kernel(const float* __restrict__ w2, const float* __restrict__ b2,
            const float* __restrict__ w3, const float* __restrict__ b3,
            const float* __restrict__ w4, const float* __restrict__ b4) {
    extern __shared__ float smem[];
    float* bufA = smem;                      // 64*256
    float* bufB = smem + NOBJ * HID;         // 64*256
    float* wt   = smem + 2 * NOBJ * HID;     // KT*256 weight tile
    float* vrow = wt + KT * HID;             // 256

    const int a1 = blockIdx.x;
    const int b  = blockIdx.y;
    const int t  = threadIdx.x;
    const int wi = t >> 5;       // warp id -> row group
    const int l  = t & 31;       // lane -> column pairs
    const int r0 = wi * 8;

    vrow[t] = g_V[(b * NOBJ + a1) * HID + t];
    __syncthreads();

    const float* Ub = g_U + (size_t)b * NOBJ * HID;
    for (int idx = t; idx < NOBJ * HID; idx += 256) {
        float hv = Ub[idx] + vrow[idx & (HID - 1)];
        bufA[idx] = hv > 0.0f ? hv : 0.0f;
    }
    __syncthreads();

    const float* Ws[3] = {w2, w3, w4};
    const float* Bs[3] = {b2, b3, b4};
    float* bin = bufA;
    float* bout = bufB;

    for (int layer = 0; layer < 3; layer++) {
        const float* W = Ws[layer];

        unsigned long long acc[8][4];
#pragma unroll
        for (int i = 0; i < 8; i++)
#pragma unroll
            for (int jj = 0; jj < 4; jj++) acc[i][jj] = 0ull;  // (0.f, 0.f)

        for (int kb = 0; kb < HID / KT; kb++) {
            // stage KT x 256 weight tile into smem (float4 vectorized)
            const float4* src = (const float4*)(W + kb * KT * HID);
            float4* dst = (float4*)wt;
            for (int i = t; i < KT * HID / 4; i += 256) dst[i] = src[i];
            __syncthreads();

            const float* arow = bin + kb * KT;
#pragma unroll 4
            for (int k = 0; k < KT; k++) {
                unsigned long long a2[8];
#pragma unroll
                for (int i = 0; i < 8; i++)
                    a2[i] = pack2(arow[(r0 + i) * HID + k]);  // warp-uniform broadcast
#pragma unroll
                for (int jj = 0; jj < 4; jj++) {
                    unsigned long long wv =
                        *(const unsigned long long*)(wt + k * HID + 2 * (l + 32 * jj));
#pragma unroll
                    for (int i = 0; i < 8; i++) acc[i][jj] = ffma2(a2[i], wv, acc[i][jj]);
                }
            }
            __syncthreads();
        }

        // epilogue: bias + relu -> bout
        const float* bias = Bs[layer];
#pragma unroll
        for (int jj = 0; jj < 4; jj++) {
            const int c = 2 * (l + 32 * jj);
            const float2 bb = *(const float2*)(bias + c);
#pragma unroll
            for (int i = 0; i < 8; i++) {
                float lo, hi;
                unpack2(acc[i][jj], lo, hi);
                lo += bb.x;
                hi += bb.y;
                float2 o;
                o.x = lo > 0.0f ? lo : 0.0f;
                o.y = hi > 0.0f ? hi : 0.0f;
                *(float2*)(bout + (r0 + i) * HID + c) = o;
            }
        }
        __syncthreads();
        float* tmp = bin; bin = bout; bout = tmp;
    }

    // bin holds h4 (64 x 256): column sums (bank-conflict-free: bank = t%32)
    float s = 0.0f;
#pragma unroll 8
    for (int row = 0; row < NOBJ; row++) s += bin[row * HID + t];
    g_PART[((size_t)b * NOBJ + a1) * HID + t] = s;
}

// ---------------------------------------------------------------------------
// Kernel 3: reduce partials -> xg, f MLP, log_softmax. One block per batch.
// ---------------------------------------------------------------------------
__global__ void final_kernel(const float* __restrict__ f1_w, const float* __restrict__ f1_b,
                             const float* __restrict__ f2_w, const float* __restrict__ f2_b,
                             const float* __restrict__ f3_w, const float* __restrict__ f3_b,
                             float* __restrict__ out) {
    __shared__ float sa[HID];
    __shared__ float sb[HID];
    __shared__ float sl[OUTC];
    __shared__ float lse;
    const int b = blockIdx.x;
    const int t = threadIdx.x;

    // xg[b, t] = sum over a1 of PART[b, a1, t]
    float s = 0.0f;
    const float* P = g_PART + (size_t)b * NOBJ * HID;
#pragma unroll 8
    for (int a1 = 0; a1 < NOBJ; a1++) s += P[a1 * HID + t];
    sa[t] = s;
    __syncthreads();

    // f1
    float acc = f1_b[t];
#pragma unroll 8
    for (int c = 0; c < HID; c++) acc += sa[c] * f1_w[c * HID + t];
    sb[t] = acc > 0.0f ? acc : 0.0f;
    __syncthreads();

    // f2
    acc = f2_b[t];
#pragma unroll 8
    for (int c = 0; c < HID; c++) acc += sb[c] * f2_w[c * HID + t];
    float y2 = acc > 0.0f ? acc : 0.0f;
    __syncthreads();
    sa[t] = y2;
    __syncthreads();

    // f3 logits
    if (t < OUTC) {
        acc = f3_b[t];
#pragma unroll 8
        for (int c = 0; c < HID; c++) acc += sa[c] * f3_w[c * OUTC + t];
        sl[t] = acc;
    }
    __syncthreads();

    if (t == 0) {
        float m = sl[0];
        for (int i = 1; i < OUTC; i++) m = fmaxf(m, sl[i]);
        float se = 0.0f;
        for (int i = 0; i < OUTC; i++) se += expf(sl[i] - m);
        lse = m + logf(se);
    }
    __syncthreads();
    if (t < OUTC) out[b * OUTC + t] = sl[t] - lse;
}

// ---------------------------------------------------------------------------
extern "C" void kernel_launch(void* const* d_in, const int* in_sizes, int n_in,
                              void* d_out, int out_size) {
    const float* x    = (const float*)d_in[0];
    const float* qst  = (const float*)d_in[1];
    const float* g1_w = (const float*)d_in[2];
    const float* g1_b = (const float*)d_in[3];
    const float* g2_w = (const float*)d_in[4];
    const float* g2_b = (const float*)d_in[5];
    const float* g3_w = (const float*)d_in[6];
    const float* g3_b = (const float*)d_in[7];
    const float* g4_w = (const float*)d_in[8];
    const float* g4_b = (const float*)d_in[9];
    const float* f1_w = (const float*)d_in[10];
    const float* f1_b = (const float*)d_in[11];
    const float* f2_w = (const float*)d_in[12];
    const float* f2_b = (const float*)d_in[13];
    const float* f3_w = (const float*)d_in[14];
    const float* f3_b = (const float*)d_in[15];
    float* out = (float*)d_out;

    const int smem_bytes = (2 * NOBJ * HID + KT * HID + HID) * (int)sizeof(float);
    cudaFuncSetAttribute(pair_kernel, cudaFuncAttributeMaxDynamicSharedMemorySize,
                         smem_bytes);

    prep_kernel<<<dim3(NOBJ, BATCH), 256>>>(x, qst, g1_w, g1_b);
    pair_kernel<<<dim3(NOBJ, BATCH), 256, smem_bytes>>>(g2_w, g2_b, g3_w, g3_b,
                                                        g4_w, g4_b);
    final_kernel<<<BATCH, 256>>>(f1_w, f1_b, f2_w, f2_b, f3_w, f3_b, out);
}

// round 6
// speedup vs baseline: 5.4436x; 5.4429x over previous
#include <cuda_runtime.h>
#include <cuda_fp16.h>
#include <cstdint>

#define BATCH 64
#define NOBJ  64
#define HID   256
#define OUTC  28

__device__ float g_U[BATCH * NOBJ * HID];
__device__ float g_V[BATCH * NOBJ * HID];
__device__ float g_PART[BATCH * NOBJ * HID];
// Packed weights: 12 global chunks (3 layers x 4 k-chunks), each 64KB:
//   [hi 64x256 fp16 swizzled | lo 64x256 fp16 swizzled]
// swizzle: phys = row*512 + ((n*2) ^ ((row&7)<<4))
__device__ __align__(128) __half g_Wpack[12 * 32768];

// ---------------- PTX helpers (sm_90-portable only!) ----------------
__device__ __forceinline__ uint32_t smem_u32(const void* p) {
    uint32_t a;
    asm("{ .reg .u64 t; cvta.to.shared.u64 t, %1; cvt.u32.u64 %0, t; }" : "=r"(a) : "l"(p));
    return a;
}
#define MBAR_INIT(addr, cnt) \
    asm volatile("mbarrier.init.shared.b64 [%0], %1;" :: "r"(addr), "r"((uint32_t)(cnt)) : "memory")
#define MBAR_EXPECT_TX(addr, n) \
    asm volatile("mbarrier.arrive.expect_tx.shared.b64 _, [%0], %1;" :: "r"(addr), "r"((uint32_t)(n)) : "memory")
#define MBAR_ARRIVE(addr) \
    asm volatile("mbarrier.arrive.shared.b64 _, [%0];" :: "r"(addr) : "memory")

__device__ __forceinline__ void mbar_wait(uint32_t mbar, uint32_t parity) {
    asm volatile(
        "{\n\t.reg .pred P1;\n\t"
        "WL_%=:\n\t"
        "mbarrier.try_wait.parity.acquire.cta.shared::cta.b64 P1, [%0], %1, 0x989680;\n\t"
        "@P1 bra.uni WD_%=;\n\t"
        "bra.uni WL_%=;\n\t"
        "WD_%=:\n\t}"
        :: "r"(mbar), "r"(parity) : "memory");
}
__device__ __forceinline__ void bulk_g2s(uint32_t dst, const void* src,
                                         uint32_t bytes, uint32_t mbar) {
    asm volatile(
        "cp.async.bulk.shared::cluster.global.mbarrier::complete_tx::bytes [%0], [%1], %2, [%3];"
        :: "r"(dst), "l"(src), "r"(bytes), "r"(mbar) : "memory");
}

#define LDSM_X4(r0, r1, r2, r3, addr) \
    asm volatile("ldmatrix.sync.aligned.m8n8.x4.shared.b16 {%0,%1,%2,%3}, [%4];" \
                 : "=r"(r0), "=r"(r1), "=r"(r2), "=r"(r3) : "r"(addr))
#define LDSM_X4_T(r0, r1, r2, r3, addr) \
    asm volatile("ldmatrix.sync.aligned.m8n8.x4.trans.shared.b16 {%0,%1,%2,%3}, [%4];" \
                 : "=r"(r0), "=r"(r1), "=r"(r2), "=r"(r3) : "r"(addr))

__device__ __forceinline__ void mma16816(float* c, const uint32_t* a, const uint32_t* b) {
    asm volatile(
        "mma.sync.aligned.m16n8k16.row.col.f32.f16.f16.f32 "
        "{%0,%1,%2,%3}, {%4,%5,%6,%7}, {%8,%9}, {%0,%1,%2,%3};"
        : "+f"(c[0]), "+f"(c[1]), "+f"(c[2]), "+f"(c[3])
        : "r"(a[0]), "r"(a[1]), "r"(a[2]), "r"(a[3]), "r"(b[0]), "r"(b[1]));
}

// ---------------- Kernel 1: U, V (g1 split by linearity) ----------------
__global__ void prep_kernel(const float* __restrict__ x, const float* __restrict__ qst,
                            const float* __restrict__ g1_w, const float* __restrict__ g1_b) {
    __shared__ float sxf[26];
    __shared__ float sq[128];
    const int b = blockIdx.y, row = blockIdx.x, t = threadIdx.x;

    if (t < 24) sxf[t] = x[(b * 24 + t) * 64 + row];
    if (t == 24) sxf[24] = ((float)row * 0.125f - 4.0f) * 0.25f;
    if (t == 25) sxf[25] = ((float)(row & 7) - 4.0f) * 0.25f;
    if (t >= 128) sq[t - 128] = qst[b * 128 + (t - 128)];
    __syncthreads();

    float u = 0.0f, v = g1_b[t];
#pragma unroll
    for (int p = 0; p < 26; p++) {
        u += sxf[p] * g1_w[p * HID + t];
        v += sxf[p] * g1_w[(26 + p) * HID + t];
    }
#pragma unroll 8
    for (int q = 0; q < 128; q++) v += sq[q] * g1_w[(52 + q) * HID + t];

    g_U[(b * NOBJ + row) * HID + t] = u;
    g_V[(b * NOBJ + row) * HID + t] = v;
}

// ---------------- Kernel 1b: pack weights hi/lo, swizzled, k-major ----------------
__global__ void prep_w_kernel(const float* __restrict__ w2, const float* __restrict__ w3,
                              const float* __restrict__ w4) {
    const int l = blockIdx.y, c = blockIdx.x;   // layer, k-chunk
    const float* W = (l == 0) ? w2 : (l == 1) ? w3 : w4;
    const int g = l * 4 + c;
    __half* hi_dst = g_Wpack + (size_t)g * 32768;
    __half* lo_dst = hi_dst + 16384;
    for (int i = threadIdx.x; i < 16384; i += 256) {
        int r = i >> 8;           // k row within chunk (0..63)
        int n = i & 255;          // output col
        float w = W[(c * 64 + r) * HID + n];
        __half hi = __float2half_rn(w);
        __half lo = __float2half_rn(w - __half2float(hi));
        int phys = (r * 512 + ((n * 2) ^ ((r & 7) << 4))) >> 1;  // half index
        hi_dst[phys] = hi;
        lo_dst[phys] = lo;
    }
}

// ---------------- Kernel 2: HMMA fused pair MLP ----------------
// SMEM: A fp16 [128x256] swizzled @0 (64KB); WBUF0 @65536; WBUF1 @131072 (64KB each);
// mbarriers @196608; bias @196672 (3*256 f32)
static constexpr int SM_A     = 0;
static constexpr int SM_WBUF0 = 65536;
static constexpr int SM_MBAR  = 196608;
static constexpr int SM_BIAS  = 196672;
static constexpr int SMEM_TOTAL = SM_BIAS + 3 * HID * 4;   // 199744 B

__global__ void __launch_bounds__(512, 1)
pair_mma_kernel(const float* __restrict__ b2, const float* __restrict__ b3,
                const float* __restrict__ b4) {
    extern __shared__ char smem[];
    const uint32_t sb = smem_u32(smem);

    const int tid = threadIdx.x;
    const int w = tid >> 5, lane = tid & 31;
    const int q = blockIdx.x, b = blockIdx.y;

    const int wm0 = (w & 1) * 64;        // warp M base (rows)
    const int wn0 = (w >> 1) * 32;       // warp N base (cols)

    const int lr = lane & 7;             // ldmatrix source row within 8
    const int sxor = lr << 4;            // swizzle XOR
    const int jr = (lane >> 3) & 1;      // +8 rows
    const int jc = lane >> 4;            // +8 cols (16B)

    const uint32_t fullb[2]  = {sb + SM_MBAR + 0,  sb + SM_MBAR + 8};
    const uint32_t emptyb[2] = {sb + SM_MBAR + 16, sb + SM_MBAR + 24};
    float* sbias = (float*)(smem + SM_BIAS);

    if (tid == 0) {
        MBAR_INIT(fullb[0], 1);   MBAR_INIT(fullb[1], 1);
        MBAR_INIT(emptyb[0], 512); MBAR_INIT(emptyb[1], 512);
    }
    if (tid < 256) {
        sbias[tid] = b2[tid];
        sbias[HID + tid] = b3[tid];
        sbias[2 * HID + tid] = b4[tid];
    }

    // ---- build A = h1 = relu(U[b,j] + V[b,a1]) as fp16, swizzled ----
    {
        const float* Ub = g_U + (size_t)b * NOBJ * HID;
        const float* V0 = g_V + ((size_t)b * NOBJ + 2 * q) * HID;
        for (int idx = tid; idx < 128 * 128; idx += 512) {
            int r = idx >> 7;            // row 0..127
            int p = idx & 127;           // k pair index
            int j = r & 63;
            const float* Vr = (r < 64) ? V0 : (V0 + HID);
            float2 uu = *(const float2*)(Ub + j * HID + 2 * p);
            float2 vv = *(const float2*)(Vr + 2 * p);
            __half2 h = __floats2half2_rn(fmaxf(uu.x + vv.x, 0.f),
                                          fmaxf(uu.y + vv.y, 0.f));
            int phys = r * 512 + ((4 * p) ^ ((r & 7) << 4));
            *(__half2*)(smem + SM_A + phys) = h;
        }
    }
    __syncthreads();

    // initial prefetch: chunks 0 and 1
    if (tid == 0) {
        MBAR_EXPECT_TX(fullb[0], 65536u);
        bulk_g2s(sb + SM_WBUF0, g_Wpack, 65536u, fullb[0]);
        MBAR_EXPECT_TX(fullb[1], 65536u);
        bulk_g2s(sb + SM_WBUF0 + 65536, g_Wpack + 32768, 65536u, fullb[1]);
    }

    float acc[4][4][4];
#pragma unroll
    for (int mi = 0; mi < 4; mi++)
#pragma unroll
        for (int ni = 0; ni < 4; ni++)
#pragma unroll
            for (int r = 0; r < 4; r++) acc[mi][ni][r] = 0.f;

    // per-lane constant address parts
    uint32_t arow[4];
#pragma unroll
    for (int mi = 0; mi < 4; mi++)
        arow[mi] = sb + SM_A + (uint32_t)(wm0 + mi * 16 + 8 * jr + lr) * 512;
    const uint32_t browoff = (uint32_t)(8 * jr + lr) * 512;
    uint32_t cbp[2];
#pragma unroll
    for (int p = 0; p < 2; p++)
        cbp[p] = (uint32_t)(((wn0 + p * 16 + jc * 8) * 2) ^ sxor);

    for (int g = 0; g < 12; g++) {
        const int buf = g & 1;
        const uint32_t wb = sb + SM_WBUF0 + buf * 65536;
        mbar_wait(fullb[buf], (g >> 1) & 1);

#pragma unroll
        for (int ks = 0; ks < 4; ks++) {
            const int kg = (g & 3) * 64 + ks * 16;
            const uint32_t acol = (uint32_t)((kg * 2 + jc * 16) ^ sxor);
            uint32_t af[4][4];
#pragma unroll
            for (int mi = 0; mi < 4; mi++)
                LDSM_X4(af[mi][0], af[mi][1], af[mi][2], af[mi][3], arow[mi] + acol);
            uint32_t bh[2][4], bl[2][4];
#pragma unroll
            for (int p = 0; p < 2; p++) {
                uint32_t ba = wb + ks * 8192 + browoff + cbp[p];
                LDSM_X4_T(bh[p][0], bh[p][1], bh[p][2], bh[p][3], ba);
                LDSM_X4_T(bl[p][0], bl[p][1], bl[p][2], bl[p][3], ba + 32768);
            }
#pragma unroll
            for (int mi = 0; mi < 4; mi++)
#pragma unroll
                for (int ni = 0; ni < 4; ni++) {
                    mma16816(acc[mi][ni], af[mi], &bh[ni >> 1][(ni & 1) * 2]);
                    mma16816(acc[mi][ni], af[mi], &bl[ni >> 1][(ni & 1) * 2]);
                }
        }
        MBAR_ARRIVE(emptyb[buf]);
        if (tid == 0 && g + 2 < 12) {  // refill this buffer with chunk g+2
            mbar_wait(emptyb[buf], (g >> 1) & 1);
            MBAR_EXPECT_TX(fullb[buf], 65536u);
            bulk_g2s(wb, g_Wpack + (size_t)(g + 2) * 32768, 65536u, fullb[buf]);
        }

        if ((g & 3) == 3) {
            const int layer = g >> 2;
            __syncthreads();   // all warps done reading A for this layer
            if (layer < 2) {
                const float* bias = sbias + layer * HID;
#pragma unroll
                for (int mi = 0; mi < 4; mi++)
#pragma unroll
                    for (int ni = 0; ni < 4; ni++) {
                        const int col = wn0 + ni * 8 + 2 * (lane & 3);
                        const float b0v = bias[col], b1v = bias[col + 1];
                        const int r0 = wm0 + mi * 16 + (lane >> 2);
                        __half2 h01 = __floats2half2_rn(
                            fmaxf(acc[mi][ni][0] + b0v, 0.f),
                            fmaxf(acc[mi][ni][1] + b1v, 0.f));
                        __half2 h23 = __floats2half2_rn(
                            fmaxf(acc[mi][ni][2] + b0v, 0.f),
                            fmaxf(acc[mi][ni][3] + b1v, 0.f));
                        const int sw = (col * 2) ^ ((r0 & 7) << 4);
                        *(__half2*)(smem + SM_A + r0 * 512 + sw) = h01;
                        *(__half2*)(smem + SM_A + (r0 + 8) * 512 + sw) = h23;
#pragma unroll
                        for (int r = 0; r < 4; r++) acc[mi][ni][r] = 0.f;
                    }
                __syncthreads();   // A ready for next layer
            } else {
                // last layer: h4 fp32 -> padded smem (stride 260 floats), then column sums
                float* hb = (float*)smem;
                const float* bias = sbias + 2 * HID;
#pragma unroll
                for (int mi = 0; mi < 4; mi++)
#pragma unroll
                    for (int ni = 0; ni < 4; ni++) {
                        const int col = wn0 + ni * 8 + 2 * (lane & 3);
                        const int r0 = wm0 + mi * 16 + (lane >> 2);
                        hb[r0 * 260 + col]           = fmaxf(acc[mi][ni][0] + bias[col], 0.f);
                        hb[r0 * 260 + col + 1]       = fmaxf(acc[mi][ni][1] + bias[col + 1], 0.f);
                        hb[(r0 + 8) * 260 + col]     = fmaxf(acc[mi][ni][2] + bias[col], 0.f);
                        hb[(r0 + 8) * 260 + col + 1] = fmaxf(acc[mi][ni][3] + bias[col + 1], 0.f);
                    }
                __syncthreads();
                const int half = tid >> 8;          // 0: rows 0-63, 1: rows 64-127
                const int col = tid & 255;
                float s = 0.f;
#pragma unroll 8
                for (int r = 0; r < 64; r++) s += hb[(half * 64 + r) * 260 + col];
                g_PART[((size_t)b * NOBJ + 2 * q + half) * HID + col] = s;
            }
        }
    }
}

// ---------------- Kernel 3: reduce + f MLP + log_softmax ----------------
__global__ void final_kernel(const float* __restrict__ f1_w, const float* __restrict__ f1_b,
                             const float* __restrict__ f2_w, const float* __restrict__ f2_b,
                             const float* __restrict__ f3_w, const float* __restrict__ f3_b,
                             float* __restrict__ out) {
    __shared__ float sa[HID];
    __shared__ float sb_[HID];
    __shared__ float sl[OUTC];
    __shared__ float lse;
    const int b = blockIdx.x, t = threadIdx.x;

    float s = 0.0f;
    const float* P = g_PART + (size_t)b * NOBJ * HID;
#pragma unroll 8
    for (int a1 = 0; a1 < NOBJ; a1++) s += P[a1 * HID + t];
    sa[t] = s;
    __syncthreads();

    float acc = f1_b[t];
#pragma unroll 8
    for (int c = 0; c < HID; c++) acc += sa[c] * f1_w[c * HID + t];
    sb_[t] = acc > 0.0f ? acc : 0.0f;
    __syncthreads();

    acc = f2_b[t];
#pragma unroll 8
    for (int c = 0; c < HID; c++) acc += sb_[c] * f2_w[c * HID + t];
    float y2 = acc > 0.0f ? acc : 0.0f;
    __syncthreads();
    sa[t] = y2;
    __syncthreads();

    if (t < OUTC) {
        acc = f3_b[t];
#pragma unroll 8
        for (int c = 0; c < HID; c++) acc += sa[c] * f3_w[c * OUTC + t];
        sl[t] = acc;
    }
    __syncthreads();

    if (t == 0) {
        float m = sl[0];
        for (int i = 1; i < OUTC; i++) m = fmaxf(m, sl[i]);
        float se = 0.0f;
        for (int i = 0; i < OUTC; i++) se += expf(sl[i] - m);
        lse = m + logf(se);
    }
    __syncthreads();
    if (t < OUTC) out[b * OUTC + t] = sl[t] - lse;
}

// ---------------------------------------------------------------------------
extern "C" void kernel_launch(void* const* d_in, const int* in_sizes, int n_in,
                              void* d_out, int out_size) {
    const float* x    = (const float*)d_in[0];
    const float* qst  = (const float*)d_in[1];
    const float* g1_w = (const float*)d_in[2];
    const float* g1_b = (const float*)d_in[3];
    const float* g2_w = (const float*)d_in[4];
    const float* g2_b = (const float*)d_in[5];
    const float* g3_w = (const float*)d_in[6];
    const float* g3_b = (const float*)d_in[7];
    const float* g4_w = (const float*)d_in[8];
    const float* g4_b = (const float*)d_in[9];
    const float* f1_w = (const float*)d_in[10];
    const float* f1_b = (const float*)d_in[11];
    const float* f2_w = (const float*)d_in[12];
    const float* f2_b = (const float*)d_in[13];
    const float* f3_w = (const float*)d_in[14];
    const float* f3_b = (const float*)d_in[15];
    float* out = (float*)d_out;

    cudaFuncSetAttribute(pair_mma_kernel, cudaFuncAttributeMaxDynamicSharedMemorySize,
                         SMEM_TOTAL);

    prep_kernel<<<dim3(NOBJ, BATCH), 256>>>(x, qst, g1_w, g1_b);
    prep_w_kernel<<<dim3(4, 3), 256>>>(g2_w, g3_w, g4_w);
    pair_mma_kernel<<<dim3(NOBJ / 2, BATCH), 512, SMEM_TOTAL>>>(g2_b, g3_b, g4_b);
    final_kernel<<<BATCH, 256>>>(f1_w, f1_b, f2_w, f2_b, f3_w, f3_b, out);
}

// round 7
// speedup vs baseline: 8.8921x; 1.6335x over previous
#include <cuda_runtime.h>
#include <cuda_fp16.h>
#include <cstdint>

#define BATCH 64
#define NOBJ  64
#define HID   256
#define OUTC  28

__device__ float g_U[BATCH * NOBJ * HID];
__device__ float g_V[BATCH * NOBJ * HID];
__device__ float g_PART[BATCH * NOBJ * HID];
__device__ float g_XG[BATCH * HID];
// Packed weights (fp16 hi only): 12 chunks (3 layers x 4 k-chunks), each 32KB
// = [64 k-rows x 256 n] fp16, swizzled: phys_byte = r*512 + ((n*2) ^ ((r&7)<<4))
__device__ __align__(128) __half g_Wpack[12 * 16384];

// ---------------- PTX helpers (sm_90-portable only) ----------------
__device__ __forceinline__ uint32_t smem_u32(const void* p) {
    uint32_t a;
    asm("{ .reg .u64 t; cvta.to.shared.u64 t, %1; cvt.u32.u64 %0, t; }" : "=r"(a) : "l"(p));
    return a;
}
#define MBAR_INIT(addr, cnt) \
    asm volatile("mbarrier.init.shared.b64 [%0], %1;" :: "r"(addr), "r"((uint32_t)(cnt)) : "memory")
#define MBAR_EXPECT_TX(addr, n) \
    asm volatile("mbarrier.arrive.expect_tx.shared.b64 _, [%0], %1;" :: "r"(addr), "r"((uint32_t)(n)) : "memory")
#define MBAR_ARRIVE(addr) \
    asm volatile("mbarrier.arrive.shared.b64 _, [%0];" :: "r"(addr) : "memory")

__device__ __forceinline__ void mbar_wait(uint32_t mbar, uint32_t parity) {
    asm volatile(
        "{\n\t.reg .pred P1;\n\t"
        "WL_%=:\n\t"
        "mbarrier.try_wait.parity.acquire.cta.shared::cta.b64 P1, [%0], %1, 0x989680;\n\t"
        "@P1 bra.uni WD_%=;\n\t"
        "bra.uni WL_%=;\n\t"
        "WD_%=:\n\t}"
        :: "r"(mbar), "r"(parity) : "memory");
}
__device__ __forceinline__ void bulk_g2s(uint32_t dst, const void* src,
                                         uint32_t bytes, uint32_t mbar) {
    asm volatile(
        "cp.async.bulk.shared::cluster.global.mbarrier::complete_tx::bytes [%0], [%1], %2, [%3];"
        :: "r"(dst), "l"(src), "r"(bytes), "r"(mbar) : "memory");
}

#define LDSM_X4(r0, r1, r2, r3, addr) \
    asm volatile("ldmatrix.sync.aligned.m8n8.x4.shared.b16 {%0,%1,%2,%3}, [%4];" \
                 : "=r"(r0), "=r"(r1), "=r"(r2), "=r"(r3) : "r"(addr))
#define LDSM_X4_T(r0, r1, r2, r3, addr) \
    asm volatile("ldmatrix.sync.aligned.m8n8.x4.trans.shared.b16 {%0,%1,%2,%3}, [%4];" \
                 : "=r"(r0), "=r"(r1), "=r"(r2), "=r"(r3) : "r"(addr))

__device__ __forceinline__ void mma16816(float* c, const uint32_t* a, const uint32_t* b) {
    asm volatile(
        "mma.sync.aligned.m16n8k16.row.col.f32.f16.f16.f32 "
        "{%0,%1,%2,%3}, {%4,%5,%6,%7}, {%8,%9}, {%0,%1,%2,%3};"
        : "+f"(c[0]), "+f"(c[1]), "+f"(c[2]), "+f"(c[3])
        : "r"(a[0]), "r"(a[1]), "r"(a[2]), "r"(a[3]), "r"(b[0]), "r"(b[1]));
}

// ---------------- Kernel 1: U, V (g1 split by linearity; qst term hoisted) ----
// grid (4, BATCH): block handles 16 rows x 256 channels. 256 threads.
__global__ void prep_kernel(const float* __restrict__ x, const float* __restrict__ qst,
                            const float* __restrict__ g1_w, const float* __restrict__ g1_b) {
    __shared__ float sxf[26][16];
    __shared__ float sq[128];
    const int b = blockIdx.y, j0 = blockIdx.x * 16, t = threadIdx.x;

    for (int i = t; i < 24 * 16; i += 256) {
        int k = i >> 4, j = i & 15;
        sxf[k][j] = x[(b * 24 + k) * 64 + j0 + j];
    }
    if (t < 16) sxf[24][t] = ((float)(j0 + t) * 0.125f - 4.0f) * 0.25f;
    else if (t < 32) {
        int j = t - 16;
        sxf[25][j] = ((float)((j0 + j) & 7) - 4.0f) * 0.25f;
    }
    if (t >= 128) sq[t - 128] = qst[b * 128 + (t - 128)];
    __syncthreads();

    // qst contribution (independent of row j)
    float vq = g1_b[t];
#pragma unroll 8
    for (int q = 0; q < 128; q++) vq += sq[q] * g1_w[(52 + q) * HID + t];

    float u[16], v[16];
#pragma unroll
    for (int j = 0; j < 16; j++) { u[j] = 0.f; v[j] = 0.f; }
#pragma unroll
    for (int p = 0; p < 26; p++) {
        float wu = g1_w[p * HID + t];
        float wv = g1_w[(26 + p) * HID + t];
#pragma unroll
        for (int j = 0; j < 16; j++) {
            float s = sxf[p][j];
            u[j] += s * wu;
            v[j] += s * wv;
        }
    }
#pragma unroll
    for (int j = 0; j < 16; j++) {
        g_U[(b * NOBJ + j0 + j) * HID + t] = u[j];
        g_V[(b * NOBJ + j0 + j) * HID + t] = v[j] + vq;
    }
}

// ---------------- Kernel 1b: pack weights fp16 (hi), swizzled, k-major -------
__global__ void prep_w_kernel(const float* __restrict__ w2, const float* __restrict__ w3,
                              const float* __restrict__ w4) {
    const int l = blockIdx.y, c = blockIdx.x;
    const float* W = (l == 0) ? w2 : (l == 1) ? w3 : w4;
    __half* dst = g_Wpack + (size_t)(l * 4 + c) * 16384;
    for (int i = threadIdx.x; i < 16384; i += 256) {
        int r = i >> 8;       // k row within chunk
        int n = i & 255;      // output col
        float w = W[(c * 64 + r) * HID + n];
        int phys = (r * 512 + ((n * 2) ^ ((r & 7) << 4))) >> 1;
        dst[phys] = __float2half_rn(w);
    }
}

// ---------------- Kernel 2: HMMA fused pair MLP (fp16 weights) ---------------
// SMEM: A fp16 [128x256] swizzled @0 (64KB); WBUF0 @65536, WBUF1 @98304 (32KB each);
// mbarriers @131072; bias @131136
static constexpr int SM_A     = 0;
static constexpr int SM_WBUF0 = 65536;
static constexpr int SM_MBAR  = 131072;
static constexpr int SM_BIAS  = 131136;
static constexpr int SMEM_TOTAL = SM_BIAS + 3 * HID * 4;   // 134208 B

__global__ void __launch_bounds__(512, 1)
pair_mma_kernel(const float* __restrict__ b2, const float* __restrict__ b3,
                const float* __restrict__ b4) {
    extern __shared__ char smem[];
    const uint32_t sb = smem_u32(smem);

    const int tid = threadIdx.x;
    const int w = tid >> 5, lane = tid & 31;
    const int q = blockIdx.x, b = blockIdx.y;

    const int wm0 = (w & 1) * 64;        // warp M base
    const int wn0 = (w >> 1) * 32;       // warp N base

    const int lr = lane & 7;
    const int sxor = lr << 4;
    const int jr = (lane >> 3) & 1;
    const int jc = lane >> 4;

    const uint32_t fullb[2]  = {sb + SM_MBAR + 0,  sb + SM_MBAR + 8};
    const uint32_t emptyb[2] = {sb + SM_MBAR + 16, sb + SM_MBAR + 24};
    float* sbias = (float*)(smem + SM_BIAS);

    if (tid == 0) {
        MBAR_INIT(fullb[0], 1);    MBAR_INIT(fullb[1], 1);
        MBAR_INIT(emptyb[0], 512); MBAR_INIT(emptyb[1], 512);
    }
    if (tid < 256) {
        sbias[tid] = b2[tid];
        sbias[HID + tid] = b3[tid];
        sbias[2 * HID + tid] = b4[tid];
    }

    // ---- A = h1 = relu(U[b,j] + V[b,a1]) as fp16, swizzled ----
    {
        const float* Ub = g_U + (size_t)b * NOBJ * HID;
        const float* V0 = g_V + ((size_t)b * NOBJ + 2 * q) * HID;
        for (int idx = tid; idx < 128 * 128; idx += 512) {
            int r = idx >> 7;
            int p = idx & 127;
            int j = r & 63;
            const float* Vr = (r < 64) ? V0 : (V0 + HID);
            float2 uu = *(const float2*)(Ub + j * HID + 2 * p);
            float2 vv = *(const float2*)(Vr + 2 * p);
            __half2 h = __floats2half2_rn(fmaxf(uu.x + vv.x, 0.f),
                                          fmaxf(uu.y + vv.y, 0.f));
            int phys = r * 512 + ((4 * p) ^ ((r & 7) << 4));
            *(__half2*)(smem + SM_A + phys) = h;
        }
    }
    __syncthreads();

    if (tid == 0) {
        MBAR_EXPECT_TX(fullb[0], 32768u);
        bulk_g2s(sb + SM_WBUF0, g_Wpack, 32768u, fullb[0]);
        MBAR_EXPECT_TX(fullb[1], 32768u);
        bulk_g2s(sb + SM_WBUF0 + 32768, g_Wpack + 16384, 32768u, fullb[1]);
    }

    float acc[4][4][4];
#pragma unroll
    for (int mi = 0; mi < 4; mi++)
#pragma unroll
        for (int ni = 0; ni < 4; ni++)
#pragma unroll
            for (int r = 0; r < 4; r++) acc[mi][ni][r] = 0.f;

    uint32_t arow[4];
#pragma unroll
    for (int mi = 0; mi < 4; mi++)
        arow[mi] = sb + SM_A + (uint32_t)(wm0 + mi * 16 + 8 * jr + lr) * 512;
    const uint32_t browoff = (uint32_t)(8 * jr + lr) * 512;
    uint32_t cbp[2];
#pragma unroll
    for (int p = 0; p < 2; p++)
        cbp[p] = (uint32_t)(((wn0 + p * 16 + jc * 8) * 2) ^ sxor);

    for (int g = 0; g < 12; g++) {
        const int buf = g & 1;
        const uint32_t wb = sb + SM_WBUF0 + buf * 32768;
        mbar_wait(fullb[buf], (g >> 1) & 1);

#pragma unroll
        for (int ks = 0; ks < 4; ks++) {
            const int kg = (g & 3) * 64 + ks * 16;
            const uint32_t acol = (uint32_t)((kg * 2 + jc * 16) ^ sxor);
            uint32_t af[4][4];
#pragma unroll
            for (int mi = 0; mi < 4; mi++)
                LDSM_X4(af[mi][0], af[mi][1], af[mi][2], af[mi][3], arow[mi] + acol);
            uint32_t bh[2][4];
#pragma unroll
            for (int p = 0; p < 2; p++) {
                uint32_t ba = wb + ks * 8192 + browoff + cbp[p];
                LDSM_X4_T(bh[p][0], bh[p][1], bh[p][2], bh[p][3], ba);
            }
#pragma unroll
            for (int mi = 0; mi < 4; mi++)
#pragma unroll
                for (int ni = 0; ni < 4; ni++)
                    mma16816(acc[mi][ni], af[mi], &bh[ni >> 1][(ni & 1) * 2]);
        }
        MBAR_ARRIVE(emptyb[buf]);
        if (tid == 0 && g + 2 < 12) {
            mbar_wait(emptyb[buf], (g >> 1) & 1);
            MBAR_EXPECT_TX(fullb[buf], 32768u);
            bulk_g2s(wb, g_Wpack + (size_t)(g + 2) * 16384, 32768u, fullb[buf]);
        }

        if ((g & 3) == 3) {
            const int layer = g >> 2;
            __syncthreads();
            if (layer < 2) {
                const float* bias = sbias + layer * HID;
#pragma unroll
                for (int mi = 0; mi < 4; mi++)
#pragma unroll
                    for (int ni = 0; ni < 4; ni++) {
                        const int col = wn0 + ni * 8 + 2 * (lane & 3);
                        const float b0v = bias[col], b1v = bias[col + 1];
                        const int r0 = wm0 + mi * 16 + (lane >> 2);
                        __half2 h01 = __floats2half2_rn(
                            fmaxf(acc[mi][ni][0] + b0v, 0.f),
                            fmaxf(acc[mi][ni][1] + b1v, 0.f));
                        __half2 h23 = __floats2half2_rn(
                            fmaxf(acc[mi][ni][2] + b0v, 0.f),
                            fmaxf(acc[mi][ni][3] + b1v, 0.f));
                        const int sw = (col * 2) ^ ((r0 & 7) << 4);
                        *(__half2*)(smem + SM_A + r0 * 512 + sw) = h01;
                        *(__half2*)(smem + SM_A + (r0 + 8) * 512 + sw) = h23;
#pragma unroll
                        for (int r = 0; r < 4; r++) acc[mi][ni][r] = 0.f;
                    }
                __syncthreads();
            } else {
                float* hb = (float*)smem;  // 128 x 260 padded fp32
                const float* bias = sbias + 2 * HID;
#pragma unroll
                for (int mi = 0; mi < 4; mi++)
#pragma unroll
                    for (int ni = 0; ni < 4; ni++) {
                        const int col = wn0 + ni * 8 + 2 * (lane & 3);
                        const int r0 = wm0 + mi * 16 + (lane >> 2);
                        hb[r0 * 260 + col]           = fmaxf(acc[mi][ni][0] + bias[col], 0.f);
                        hb[r0 * 260 + col + 1]       = fmaxf(acc[mi][ni][1] + bias[col + 1], 0.f);
                        hb[(r0 + 8) * 260 + col]     = fmaxf(acc[mi][ni][2] + bias[col], 0.f);
                        hb[(r0 + 8) * 260 + col + 1] = fmaxf(acc[mi][ni][3] + bias[col + 1], 0.f);
                    }
                __syncthreads();
                const int half = tid >> 8;
                const int col = tid & 255;
                float s = 0.f;
#pragma unroll 8
                for (int r = 0; r < 64; r++) s += hb[(half * 64 + r) * 260 + col];
                g_PART[((size_t)b * NOBJ + 2 * q + half) * HID + col] = s;
            }
        }
    }
}

// ---------------- Kernel 3a: reduce g_PART over a1 -> g_XG -------------------
__global__ void reduce_kernel() {
    __shared__ float red[1024];
    const int b = blockIdx.x, t = threadIdx.x;
    const int ch = t & 255, seg = t >> 8;
    const float* P = g_PART + (size_t)b * NOBJ * HID;
    float s = 0.f;
#pragma unroll
    for (int a1 = seg; a1 < NOBJ; a1 += 4) s += P[a1 * HID + ch];
    red[t] = s;
    __syncthreads();
    if (t < 256) g_XG[b * HID + t] = red[t] + red[t + 256] + red[t + 512] + red[t + 768];
}

// ---------------- Kernel 3b: f MLP + log_softmax -----------------------------
__global__ void f_kernel(const float* __restrict__ f1_w, const float* __restrict__ f1_b,
                         const float* __restrict__ f2_w, const float* __restrict__ f2_b,
                         const float* __restrict__ f3_w, const float* __restrict__ f3_b,
                         float* __restrict__ out) {
    __shared__ float sa[HID];
    __shared__ float sb_[HID];
    __shared__ float sl[OUTC];
    __shared__ float lse;
    const int b = blockIdx.x, t = threadIdx.x;

    sa[t] = g_XG[b * HID + t];
    __syncthreads();

    float acc = f1_b[t];
#pragma unroll 8
    for (int c = 0; c < HID; c++) acc += sa[c] * f1_w[c * HID + t];
    sb_[t] = acc > 0.0f ? acc : 0.0f;
    __syncthreads();

    acc = f2_b[t];
#pragma unroll 8
    for (int c = 0; c < HID; c++) acc += sb_[c] * f2_w[c * HID + t];
    float y2 = acc > 0.0f ? acc : 0.0f;
    __syncthreads();
    sa[t] = y2;
    __syncthreads();

    if (t < OUTC) {
        acc = f3_b[t];
#pragma unroll 8
        for (int c = 0; c < HID; c++) acc += sa[c] * f3_w[c * OUTC + t];
        sl[t] = acc;
    }
    __syncthreads();

    if (t == 0) {
        float m = sl[0];
        for (int i = 1; i < OUTC; i++) m = fmaxf(m, sl[i]);
        float se = 0.0f;
        for (int i = 0; i < OUTC; i++) se += expf(sl[i] - m);
        lse = m + logf(se);
    }
    __syncthreads();
    if (t < OUTC) out[b * OUTC + t] = sl[t] - lse;
}

// ---------------------------------------------------------------------------
extern "C" void kernel_launch(void* const* d_in, const int* in_sizes, int n_in,
                              void* d_out, int out_size) {
    const float* x    = (const float*)d_in[0];
    const float* qst  = (const float*)d_in[1];
    const float* g1_w = (const float*)d_in[2];
    const float* g1_b = (const float*)d_in[3];
    const float* g2_w = (const float*)d_in[4];
    const float* g2_b = (const float*)d_in[5];
    const float* g3_w = (const float*)d_in[6];
    const float* g3_b = (const float*)d_in[7];
    const float* g4_w = (const float*)d_in[8];
    const float* g4_b = (const float*)d_in[9];
    const float* f1_w = (const float*)d_in[10];
    const float* f1_b = (const float*)d_in[11];
    const float* f2_w = (const float*)d_in[12];
    const float* f2_b = (const float*)d_in[13];
    const float* f3_w = (const float*)d_in[14];
    const float* f3_b = (const float*)d_in[15];
    float* out = (float*)d_out;

    cudaFuncSetAttribute(pair_mma_kernel, cudaFuncAttributeMaxDynamicSharedMemorySize,
                         SMEM_TOTAL);

    prep_kernel<<<dim3(4, BATCH), 256>>>(x, qst, g1_w, g1_b);
    prep_w_kernel<<<dim3(4, 3), 256>>>(g2_w, g3_w, g4_w);
    pair_mma_kernel<<<dim3(NOBJ / 2, BATCH), 512, SMEM_TOTAL>>>(g2_b, g3_b, g4_b);
    reduce_kernel<<<BATCH, 1024>>>();
    f_kernel<<<BATCH, 256>>>(f1_w, f1_b, f2_w, f2_b, f3_w, f3_b, out);
}